// round 16
// baseline (speedup 1.0000x reference)
#include <cuda_runtime.h>
#include <cuda_bf16.h>
#include <cstdint>

typedef unsigned long long ull;

#define TPB      256
#define NLAYERS  31
#define N_HIDDEN 30
#define H        16
#define S_IN     13

#define MREP     6                 // HMMA warps: 6 m-tiles = 96 samples/warp
#define H_SAMP   (4 * 16 * MREP)   // 384 samples via 4 HMMA warps
#define NS       2                 // scalar warps: 2 samples/thread
#define S_SAMP   (4 * 32 * NS)     // 256 samples via 4 scalar warps
#define SPC      (H_SAMP + S_SAMP) // 640 samples per CTA

// ================= scalar-path f32x2 helpers =================
__device__ __forceinline__ ull pack2(float lo, float hi){
    ull r; asm("mov.b64 %0, {%1, %2};" : "=l"(r) : "f"(lo), "f"(hi)); return r;
}
__device__ __forceinline__ ull dup2(float v){
    ull r; asm("mov.b64 %0, {%1, %1};" : "=l"(r) : "f"(v)); return r;
}
__device__ __forceinline__ void unpack2(ull v, float& lo, float& hi){
    asm("mov.b64 {%0, %1}, %2;" : "=f"(lo), "=f"(hi) : "l"(v));
}
__device__ __forceinline__ ull fma2(ull a, ull b, ull c){
    ull d; asm("fma.rn.f32x2 %0, %1, %2, %3;" : "=l"(d) : "l"(a), "l"(b), "l"(c)); return d;
}

// ================= HMMA-path bf16 helpers (R13 exact forms) =================
__device__ __forceinline__ uint32_t cvt_bf16x2(float a, float b){
    uint32_t r;
    asm("cvt.rn.satfinite.bf16x2.f32 %0, %1, %2;" : "=r"(r) : "f"(b), "f"(a));
    return r;
}
__device__ __forceinline__ void split_pair(float a, float b, uint32_t& hi, uint32_t& lo){
    hi = cvt_bf16x2(a, b);
    float fa = __uint_as_float(hi << 16);
    float fb = __uint_as_float(hi & 0xFFFF0000u);
    lo = cvt_bf16x2(a - fa, b - fb);
}
__device__ __forceinline__ void relu_split(float d0, float d1, uint32_t& hi, uint32_t& lo){
    uint32_t h;
    asm("cvt.rz.relu.satfinite.bf16x2.f32 %0, %1, %2;" : "=r"(h) : "f"(d1), "f"(d0));
    float fa = __uint_as_float(h * 65536u);        // IMAD -> fma pipe
    float fb = __uint_as_float(h & 0xFFFF0000u);   // LOP3
    uint32_t lo_;
    asm("cvt.rn.relu.satfinite.bf16x2.f32 %0, %1, %2;" : "=r"(lo_)
        : "f"(d1 - fb), "f"(d0 - fa));
    hi = h; lo = lo_;
}
__device__ __forceinline__ void mma16816(float d[4], const uint32_t a[4],
                                         uint32_t b0, uint32_t b1){
    asm volatile(
        "mma.sync.aligned.m16n8k16.row.col.f32.bf16.bf16.f32 "
        "{%0,%1,%2,%3}, {%4,%5,%6,%7}, {%8,%9}, {%0,%1,%2,%3};"
        : "+f"(d[0]), "+f"(d[1]), "+f"(d[2]), "+f"(d[3])
        : "r"(a[0]), "r"(a[1]), "r"(a[2]), "r"(a[3]), "r"(b0), "r"(b1));
}
__device__ __forceinline__ void mma16816_c(float d[4], const uint32_t a[4],
                                           uint32_t b0, uint32_t b1,
                                           float c0, float c1){
    asm volatile(
        "mma.sync.aligned.m16n8k16.row.col.f32.bf16.bf16.f32 "
        "{%0,%1,%2,%3}, {%4,%5,%6,%7}, {%8,%9}, {%10,%11,%10,%11};"
        : "=f"(d[0]), "=f"(d[1]), "=f"(d[2]), "=f"(d[3])
        : "r"(a[0]), "r"(a[1]), "r"(a[2]), "r"(a[3]), "r"(b0), "r"(b1),
          "f"(c0), "f"(c1));
}

// ================= shared memory (both layouts live; dynamic) =================
struct HmmaSmem {
    uint4  wf[NLAYERS][2][32];
    float4 b4[NLAYERS][4];
    float  wout[16];
    float  bout;
};
struct ScalSmem {
    ull   win[S_IN * 8];
    ull   bin[8];
    ull   wh[N_HIDDEN * H * 8];
    ull   bh[N_HIDDEN * 8];
    ull   wout[8];
    float bout;
};
struct BothSmem { HmmaSmem h; ScalSmem s; };

__global__ __launch_bounds__(TPB, 2)
void mlp_ws_kernel(const float* __restrict__ x,
                   const float* __restrict__ W_in,  const float* __restrict__ b_in,
                   const float* __restrict__ W_h,   const float* __restrict__ b_h,
                   const float* __restrict__ W_out, const float* __restrict__ b_out,
                   float* __restrict__ out, int B)
{
    extern __shared__ __align__(16) char dynsm[];
    BothSmem& SM = *reinterpret_cast<BothSmem*>(dynsm);

    const int t = threadIdx.x;

    // ---- prep: HMMA fragments ----
    for (int e = t; e < NLAYERS * 2 * 32; e += TPB){
        int l = e >> 6, r = e & 63, tile = r >> 5, tt = r & 31;
        int n = (tt >> 2) + tile * 8, i = tt & 3;
        float w[4];
#pragma unroll
        for (int j = 0; j < 4; j++){
            int k = 2*i + (j & 1) + (j >> 1) * 8;
            if (l == 0) w[j] = (k < S_IN) ? W_in[n * S_IN + k] : 0.f;
            else        w[j] = W_h[(l - 1) * (H * H) + n * H + k];
        }
        uint32_t h0, l0, h1, l1;
        split_pair(w[0], w[1], h0, l0);
        split_pair(w[2], w[3], h1, l1);
        SM.h.wf[l][tile][tt] = make_uint4(h0, h1, l0, l1);
    }
    for (int e = t; e < NLAYERS * 4; e += TPB){
        int l = e >> 2, i = e & 3;
        const float* bb = (l == 0) ? b_in : (b_h + (l - 1) * H);
        SM.h.b4[l][i] = make_float4(bb[2*i], bb[2*i+1], bb[2*i+8], bb[2*i+9]);
    }
    if (t < 16) SM.h.wout[t] = W_out[t];
    if (t == 0) SM.h.bout = b_out[0];

    // ---- prep: scalar j-pair layout ----
    for (int i = t; i < S_IN * 8; i += TPB){
        int k = i >> 3, jp = i & 7;
        SM.s.win[i] = pack2(W_in[(2*jp)*S_IN + k], W_in[(2*jp+1)*S_IN + k]);
    }
    if (t >= 32 && t < 40){
        int q = t - 32;
        SM.s.bin[q]  = pack2(b_in[2*q],  b_in[2*q+1]);
        SM.s.wout[q] = pack2(W_out[2*q], W_out[2*q+1]);
    }
    for (int i = t; i < N_HIDDEN * H * 8; i += TPB){
        int l = i >> 7; int r = i & 127; int k = r >> 3, jp = r & 7;
        const float* Wl = W_h + l * (H * H);
        SM.s.wh[i] = pack2(Wl[(2*jp)*H + k], Wl[(2*jp+1)*H + k]);
    }
    for (int i = t; i < N_HIDDEN * 8; i += TPB){
        int l = i >> 3, jp = i & 7;
        SM.s.bh[i] = pack2(b_h[l*H + 2*jp], b_h[l*H + 2*jp + 1]);
    }
    if (t == 1) SM.s.bout = b_out[0];
    __syncthreads();

    const int wid  = t >> 5;
    const int lane = t & 31;
    const int cb   = blockIdx.x * SPC;

    if (wid < 4){
        // ================= HMMA role (one warp per SMSP) =================
        HmmaSmem& S = SM.h;
        const int g    = lane >> 2;
        const int i4   = lane & 3;
        const int base = cb + wid * (MREP * 16);

        uint32_t Ahi[MREP][4], Alo[MREP][4];
#pragma unroll
        for (int m = 0; m < MREP; m++){
            int r0 = base + m*16 + g;     if (r0 >= B) r0 = B - 1;
            int r1 = base + m*16 + g + 8; if (r1 >= B) r1 = B - 1;
            const float* x0 = x + (size_t)r0 * S_IN;
            const float* x1 = x + (size_t)r1 * S_IN;
            float v0[4], v1[4];
#pragma unroll
            for (int j = 0; j < 4; j++){
                int k = 2*i4 + (j & 1) + (j >> 1) * 8;
                v0[j] = (k < S_IN) ? x0[k] : 0.f;
                v1[j] = (k < S_IN) ? x1[k] : 0.f;
            }
            split_pair(v0[0], v0[1], Ahi[m][0], Alo[m][0]);
            split_pair(v1[0], v1[1], Ahi[m][1], Alo[m][1]);
            split_pair(v0[2], v0[3], Ahi[m][2], Alo[m][2]);
            split_pair(v1[2], v1[3], Ahi[m][3], Alo[m][3]);
        }

#pragma unroll 1
        for (int l = 0; l < NLAYERS - 1; l++){
            uint4  wf0 = S.wf[l][0][lane];
            uint4  wf1 = S.wf[l][1][lane];
            float4 b4  = S.b4[l][i4];
#pragma unroll
            for (int m = 0; m < MREP; m++){
                float d0[4], d1[4];
                mma16816_c(d0, Ahi[m], wf0.x, wf0.y, b4.x, b4.y);
                mma16816  (d0, Ahi[m], wf0.z, wf0.w);
                mma16816  (d0, Alo[m], wf0.x, wf0.y);
                mma16816_c(d1, Ahi[m], wf1.x, wf1.y, b4.z, b4.w);
                mma16816  (d1, Ahi[m], wf1.z, wf1.w);
                mma16816  (d1, Alo[m], wf1.x, wf1.y);

                relu_split(d0[0], d0[1], Ahi[m][0], Alo[m][0]);
                relu_split(d0[2], d0[3], Ahi[m][1], Alo[m][1]);
                relu_split(d1[0], d1[1], Ahi[m][2], Alo[m][2]);
                relu_split(d1[2], d1[3], Ahi[m][3], Alo[m][3]);
            }
        }

        {
            const int l = NLAYERS - 1;
            uint4  wf0 = S.wf[l][0][lane];
            uint4  wf1 = S.wf[l][1][lane];
            float4 b4  = S.b4[l][i4];
            float wo0 = S.wout[2*i4],     wo1 = S.wout[2*i4 + 1];
            float wo2 = S.wout[2*i4 + 8], wo3 = S.wout[2*i4 + 9];
#pragma unroll
            for (int m = 0; m < MREP; m++){
                float d0[4], d1[4];
                mma16816_c(d0, Ahi[m], wf0.x, wf0.y, b4.x, b4.y);
                mma16816_c(d1, Ahi[m], wf1.x, wf1.y, b4.z, b4.w);
                mma16816  (d0, Ahi[m], wf0.z, wf0.w);
                mma16816  (d1, Ahi[m], wf1.z, wf1.w);
                mma16816  (d0, Alo[m], wf0.x, wf0.y);
                mma16816  (d1, Alo[m], wf1.x, wf1.y);

                float p0 = fmaxf(d0[0], 0.f) * wo0 + fmaxf(d0[1], 0.f) * wo1
                         + fmaxf(d1[0], 0.f) * wo2 + fmaxf(d1[1], 0.f) * wo3;
                float p1 = fmaxf(d0[2], 0.f) * wo0 + fmaxf(d0[3], 0.f) * wo1
                         + fmaxf(d1[2], 0.f) * wo2 + fmaxf(d1[3], 0.f) * wo3;
                p0 += __shfl_xor_sync(0xFFFFFFFFu, p0, 1);
                p0 += __shfl_xor_sync(0xFFFFFFFFu, p0, 2);
                p1 += __shfl_xor_sync(0xFFFFFFFFu, p1, 1);
                p1 += __shfl_xor_sync(0xFFFFFFFFu, p1, 2);
                if (i4 == 0){
                    int s0 = base + m*16 + g;
                    if (s0     < B) out[s0]     = p0 + S.bout;
                    if (s0 + 8 < B) out[s0 + 8] = p1 + S.bout;
                }
            }
        }
    } else {
        // ================= scalar FFMA2 role (one warp per SMSP) =================
        ScalSmem& S = SM.s;
        const int sl = (wid - 4) * 32 + lane;       // 0..127
        int  si[NS];
        bool va[NS];
#pragma unroll
        for (int s = 0; s < NS; s++){
            int idx = cb + H_SAMP + sl + s * 128;
            va[s] = (idx < B);
            si[s] = va[s] ? idx : (B - 1);
        }

        float h[NS][H];
        {
            ull a[NS][8];
#pragma unroll
            for (int k = 0; k < S_IN; k++){
                ull hk[NS];
#pragma unroll
                for (int s = 0; s < NS; s++)
                    hk[s] = dup2(x[(size_t)si[s] * S_IN + k]);
#pragma unroll
                for (int jp = 0; jp < 8; jp++){
                    ull w = S.win[k*8 + jp];
#pragma unroll
                    for (int s = 0; s < NS; s++)
                        a[s][jp] = fma2(w, hk[s], (k == 0) ? S.bin[jp] : a[s][jp]);
                }
            }
#pragma unroll
            for (int s = 0; s < NS; s++)
#pragma unroll
                for (int jp = 0; jp < 8; jp++){
                    float lo, hi; unpack2(a[s][jp], lo, hi);
                    h[s][2*jp]   = fmaxf(lo, 0.f);
                    h[s][2*jp+1] = fmaxf(hi, 0.f);
                }
        }

        const ull* wl = S.wh;
        const ull* bl = S.bh;
#pragma unroll 1
        for (int l = 0; l < N_HIDDEN; l++){
            ull a[NS][8];
#pragma unroll
            for (int k = 0; k < H; k++){
                ull hk[NS];
#pragma unroll
                for (int s = 0; s < NS; s++) hk[s] = dup2(h[s][k]);
                const ulonglong2* wk = reinterpret_cast<const ulonglong2*>(wl + k*8);
                ulonglong2 w01 = wk[0], w23 = wk[1], w45 = wk[2], w67 = wk[3];
                ull w[8] = {w01.x, w01.y, w23.x, w23.y, w45.x, w45.y, w67.x, w67.y};
#pragma unroll
                for (int jp = 0; jp < 8; jp++){
#pragma unroll
                    for (int s = 0; s < NS; s++)
                        a[s][jp] = fma2(w[jp], hk[s], (k == 0) ? bl[jp] : a[s][jp]);
                }
            }
#pragma unroll
            for (int s = 0; s < NS; s++)
#pragma unroll
                for (int jp = 0; jp < 8; jp++){
                    float lo, hi; unpack2(a[s][jp], lo, hi);
                    h[s][2*jp]   = fmaxf(lo, 0.f);
                    h[s][2*jp+1] = fmaxf(hi, 0.f);
                }
            wl += H * 8;
            bl += 8;
        }

#pragma unroll
        for (int s = 0; s < NS; s++){
            ull acc = pack2(S.bout, 0.f);
#pragma unroll
            for (int i = 0; i < 8; i++)
                acc = fma2(S.wout[i], pack2(h[s][2*i], h[s][2*i+1]), acc);
            float lo, hi; unpack2(acc, lo, hi);
            if (va[s]) out[si[s]] = lo + hi;
        }
    }
}

extern "C" void kernel_launch(void* const* d_in, const int* in_sizes, int n_in,
                              void* d_out, int out_size)
{
    const float* x     = (const float*)d_in[0];
    const float* W_in  = (const float*)d_in[1];
    const float* b_in  = (const float*)d_in[2];
    const float* W_h   = (const float*)d_in[3];
    const float* b_h   = (const float*)d_in[4];
    const float* W_out = (const float*)d_in[5];
    const float* b_out = (const float*)d_in[6];
    float* out = (float*)d_out;

    int B = out_size;                      // 2^21
    int grid = (B + SPC - 1) / SPC;        // 3277

    size_t smem = sizeof(BothSmem);        // ~67.4 KB > 48 KB -> opt-in
    cudaFuncSetAttribute(mlp_ws_kernel, cudaFuncAttributeMaxDynamicSharedMemorySize,
                         (int)smem);
    mlp_ws_kernel<<<grid, TPB, smem>>>(x, W_in, b_in, W_h, b_h, W_out, b_out, out, B);
}

// round 17
// speedup vs baseline: 1.5567x; 1.5567x over previous
#include <cuda_runtime.h>
#include <cuda_bf16.h>
#include <cstdint>

#define TPB      256
#define MREP     6              // m16 tiles per warp
#define SPW      (MREP * 16)    // 96 samples per warp
#define NWARP    (TPB / 32)
#define SPC      (SPW * NWARP)  // 768 samples per CTA
#define NLAYERS  31             // input layer + 30 hidden
#define H        16
#define S_IN     13

// pack two f32 into bf16x2 (low half = a, high half = b), round-to-nearest
__device__ __forceinline__ uint32_t cvt_bf16x2(float a, float b){
    uint32_t r;
    asm("cvt.rn.satfinite.bf16x2.f32 %0, %1, %2;" : "=r"(r) : "f"(b), "f"(a));
    return r;
}
// RN split (a,b) -> hi + lo bf16x2 (setup only; preserves sign)
__device__ __forceinline__ void split_pair(float a, float b, uint32_t& hi, uint32_t& lo){
    hi = cvt_bf16x2(a, b);
    float fa = __uint_as_float(hi << 16);
    float fb = __uint_as_float(hi & 0xFFFF0000u);
    lo = cvt_bf16x2(a - fa, b - fb);
}

// fused ReLU + truncation split (R13 exact form):
//   hi = relu(rz_bf16(d))  -- cvt.rz.relu (alu)
//   fa via IMAD (fma pipe), fb via LOP3 (alu)
//   lo = relu-cvt(d - {fa,fb}) -- cvt (alu); residual in [0, ulp) for d>=0
__device__ __forceinline__ void relu_split(float d0, float d1, uint32_t& hi, uint32_t& lo){
    uint32_t h;
    asm("cvt.rz.relu.satfinite.bf16x2.f32 %0, %1, %2;" : "=r"(h) : "f"(d1), "f"(d0));
    float fa = __uint_as_float(h * 65536u);        // IMAD -> fma pipe
    float fb = __uint_as_float(h & 0xFFFF0000u);   // LOP3
    uint32_t lo_;
    asm("cvt.rn.relu.satfinite.bf16x2.f32 %0, %1, %2;" : "=r"(lo_)
        : "f"(d1 - fb), "f"(d0 - fa));
    hi = h; lo = lo_;
}

// D += A(16x16 bf16, row) * B(16x8 bf16, col)
__device__ __forceinline__ void mma16816(float d[4], const uint32_t a[4],
                                         uint32_t b0, uint32_t b1){
    asm volatile(
        "mma.sync.aligned.m16n8k16.row.col.f32.bf16.bf16.f32 "
        "{%0,%1,%2,%3}, {%4,%5,%6,%7}, {%8,%9}, {%0,%1,%2,%3};"
        : "+f"(d[0]), "+f"(d[1]), "+f"(d[2]), "+f"(d[3])
        : "r"(a[0]), "r"(a[1]), "r"(a[2]), "r"(a[3]), "r"(b0), "r"(b1));
}
// D = A*B + C  (C = bias fragment; starts the accumulator chain)
__device__ __forceinline__ void mma16816_c(float d[4], const uint32_t a[4],
                                           uint32_t b0, uint32_t b1,
                                           float c0, float c1){
    asm volatile(
        "mma.sync.aligned.m16n8k16.row.col.f32.bf16.bf16.f32 "
        "{%0,%1,%2,%3}, {%4,%5,%6,%7}, {%8,%9}, {%10,%11,%10,%11};"
        : "=f"(d[0]), "=f"(d[1]), "=f"(d[2]), "=f"(d[3])
        : "r"(a[0]), "r"(a[1]), "r"(a[2]), "r"(a[3]), "r"(b0), "r"(b1),
          "f"(c0), "f"(c1));
}

__global__ __launch_bounds__(TPB, 2)
void mlp_hmma_kernel(const float* __restrict__ x,
                     const float* __restrict__ W_in,  const float* __restrict__ b_in,
                     const float* __restrict__ W_h,   const float* __restrict__ b_h,
                     const float* __restrict__ W_out, const float* __restrict__ b_out,
                     float* __restrict__ out, int B)
{
    // B-fragments per lane: {whi_r0, whi_r1, wlo_r0, wlo_r1} -> one LDS.128/tile/layer
    __shared__ uint4  s_wf[NLAYERS][2][32];
    __shared__ float4 s_b4[NLAYERS][4];
    __shared__ float  s_wout[16];
    __shared__ float  s_bout;

    const int t = threadIdx.x;

    // ---- weight prep: fragment order, bf16 hi/lo (RN split) ----
    for (int e = t; e < NLAYERS * 2 * 32; e += TPB){
        int l = e >> 6, r = e & 63, tile = r >> 5, tt = r & 31;
        int n = (tt >> 2) + tile * 8, i = tt & 3;
        float w[4];
#pragma unroll
        for (int j = 0; j < 4; j++){
            int k = 2*i + (j & 1) + (j >> 1) * 8;
            if (l == 0) w[j] = (k < S_IN) ? W_in[n * S_IN + k] : 0.f;
            else        w[j] = W_h[(l - 1) * (H * H) + n * H + k];
        }
        uint32_t h0, l0, h1, l1;
        split_pair(w[0], w[1], h0, l0);
        split_pair(w[2], w[3], h1, l1);
        s_wf[l][tile][tt] = make_uint4(h0, h1, l0, l1);
    }
    for (int e = t; e < NLAYERS * 4; e += TPB){
        int l = e >> 2, i = e & 3;
        const float* bb = (l == 0) ? b_in : (b_h + (l - 1) * H);
        s_b4[l][i] = make_float4(bb[2*i], bb[2*i+1], bb[2*i+8], bb[2*i+9]);
    }
    if (t < 16) s_wout[t] = W_out[t];
    if (t == 0) s_bout = b_out[0];
    __syncthreads();

    const int wid  = t >> 5;
    const int lane = t & 31;
    const int g    = lane >> 2;     // row group (0..7)
    const int i4   = lane & 3;      // col group (0..3)
    const int base = blockIdx.x * SPC + wid * SPW;

    // ---- A fragments for round 0 (load-clamped for tail CTA) ----
    uint32_t Ahi[MREP][4], Alo[MREP][4];
#pragma unroll
    for (int m = 0; m < MREP; m++){
        int r0 = base + m*16 + g;     if (r0 >= B) r0 = B - 1;
        int r1 = base + m*16 + g + 8; if (r1 >= B) r1 = B - 1;
        const float* x0 = x + (size_t)r0 * S_IN;
        const float* x1 = x + (size_t)r1 * S_IN;
        float v0[4], v1[4];
#pragma unroll
        for (int j = 0; j < 4; j++){
            int k = 2*i4 + (j & 1) + (j >> 1) * 8;
            v0[j] = (k < S_IN) ? x0[k] : 0.f;
            v1[j] = (k < S_IN) ? x1[k] : 0.f;
        }
        split_pair(v0[0], v0[1], Ahi[m][0], Alo[m][0]);
        split_pair(v1[0], v1[1], Ahi[m][1], Alo[m][1]);
        split_pair(v0[2], v0[3], Ahi[m][2], Alo[m][2]);
        split_pair(v1[2], v1[3], Ahi[m][3], Alo[m][3]);
    }

    // ---- 30 chained layers: d = Ahi*Whi + bias; d += Ahi*Wlo; d += Alo*Whi ----
#pragma unroll 1
    for (int l = 0; l < NLAYERS - 1; l++){
        uint4  wf0 = s_wf[l][0][lane];
        uint4  wf1 = s_wf[l][1][lane];
        float4 b4  = s_b4[l][i4];
#pragma unroll
        for (int m = 0; m < MREP; m++){
            float d0[4], d1[4];
            mma16816_c(d0, Ahi[m], wf0.x, wf0.y, b4.x, b4.y);
            mma16816  (d0, Ahi[m], wf0.z, wf0.w);
            mma16816  (d0, Alo[m], wf0.x, wf0.y);
            mma16816_c(d1, Ahi[m], wf1.x, wf1.y, b4.z, b4.w);
            mma16816  (d1, Ahi[m], wf1.z, wf1.w);
            mma16816  (d1, Alo[m], wf1.x, wf1.y);

            relu_split(d0[0], d0[1], Ahi[m][0], Alo[m][0]);
            relu_split(d0[2], d0[3], Ahi[m][1], Alo[m][1]);
            relu_split(d1[0], d1[1], Ahi[m][2], Alo[m][2]);
            relu_split(d1[2], d1[3], Ahi[m][3], Alo[m][3]);
        }
    }

    // ---- final hidden layer + output dot, fused ----
    {
        const int l = NLAYERS - 1;
        uint4  wf0 = s_wf[l][0][lane];
        uint4  wf1 = s_wf[l][1][lane];
        float4 b4  = s_b4[l][i4];
        float wo0 = s_wout[2*i4],     wo1 = s_wout[2*i4 + 1];
        float wo2 = s_wout[2*i4 + 8], wo3 = s_wout[2*i4 + 9];
#pragma unroll
        for (int m = 0; m < MREP; m++){
            float d0[4], d1[4];
            mma16816_c(d0, Ahi[m], wf0.x, wf0.y, b4.x, b4.y);
            mma16816_c(d1, Ahi[m], wf1.x, wf1.y, b4.z, b4.w);
            mma16816  (d0, Ahi[m], wf0.z, wf0.w);
            mma16816  (d1, Ahi[m], wf1.z, wf1.w);
            mma16816  (d0, Alo[m], wf0.x, wf0.y);
            mma16816  (d1, Alo[m], wf1.x, wf1.y);

            float p0 = fmaxf(d0[0], 0.f) * wo0 + fmaxf(d0[1], 0.f) * wo1
                     + fmaxf(d1[0], 0.f) * wo2 + fmaxf(d1[1], 0.f) * wo3;
            float p1 = fmaxf(d0[2], 0.f) * wo0 + fmaxf(d0[3], 0.f) * wo1
                     + fmaxf(d1[2], 0.f) * wo2 + fmaxf(d1[3], 0.f) * wo3;
            p0 += __shfl_xor_sync(0xFFFFFFFFu, p0, 1);
            p0 += __shfl_xor_sync(0xFFFFFFFFu, p0, 2);
            p1 += __shfl_xor_sync(0xFFFFFFFFu, p1, 1);
            p1 += __shfl_xor_sync(0xFFFFFFFFu, p1, 2);
            if (i4 == 0){
                int s0 = base + m*16 + g;
                if (s0     < B) out[s0]     = p0 + s_bout;
                if (s0 + 8 < B) out[s0 + 8] = p1 + s_bout;
            }
        }
    }
}

extern "C" void kernel_launch(void* const* d_in, const int* in_sizes, int n_in,
                              void* d_out, int out_size)
{
    const float* x     = (const float*)d_in[0];
    const float* W_in  = (const float*)d_in[1];
    const float* b_in  = (const float*)d_in[2];
    const float* W_h   = (const float*)d_in[3];
    const float* b_h   = (const float*)d_in[4];
    const float* W_out = (const float*)d_in[5];
    const float* b_out = (const float*)d_in[6];
    float* out = (float*)d_out;

    int B = out_size;                    // 2^21
    int grid = (B + SPC - 1) / SPC;      // 2731 (last CTA partial, guarded)
    mlp_hmma_kernel<<<grid, TPB>>>(x, W_in, b_in, W_h, b_h, W_out, b_out, out, B);
}